// round 9
// baseline (speedup 1.0000x reference)
#include <cuda_runtime.h>
#include <cuda_bf16.h>
#include <math.h>
#include <stdint.h>

// Problem constants
#define BN   4
#define CN   256
#define HN   64
#define WN   64
#define HWN  4096
#define CHWN (CN * HWN)     // 1048576
#define SCALE 0.0625f       // 1/sqrt(256)

// ---------------------------------------------------------------------------
// Scratch (device globals; no allocations allowed)
// ---------------------------------------------------------------------------
__device__ float g_Q [BN * CHWN];            // fp32 Q, [b][c][n]  (for Q_mask)
__device__ float g_V [BN * CHWN];            // fp32 V, [b][c][n]
__device__ __nv_bfloat16 g_Qb[BN * CHWN];    // bf16 Q, TRANSPOSED [b][n][c]
__device__ __nv_bfloat16 g_Kb[BN * CHWN];    // bf16 K, TRANSPOSED [b][m][c]
__device__ float g_colmax[BN * HWN];         // max over n of soft[b,n,m]  (positive)
__device__ float g_Qmask[4 * HWN];           // indexed by (c%4)*4096 + n
__device__ float g_m2[BN * HN];              // indexed by b*64 + h_k

__device__ __forceinline__ void cpasync16(void* dst, const void* src) {
    unsigned s = (unsigned)__cvta_generic_to_shared(dst);
    asm volatile("cp.async.cg.shared.global [%0], [%1], 16;\n" :: "r"(s), "l"(src));
}
__device__ __forceinline__ void cpcommit() { asm volatile("cp.async.commit_group;\n"); }

__device__ __forceinline__ void ldmx4(uint32_t& r0, uint32_t& r1, uint32_t& r2, uint32_t& r3,
                                      uint32_t addr) {
    asm volatile("ldmatrix.sync.aligned.m8n8.x4.shared.b16 {%0,%1,%2,%3}, [%4];"
                 : "=r"(r0), "=r"(r1), "=r"(r2), "=r"(r3) : "r"(addr));
}

// ---------------------------------------------------------------------------
// 0) zero colmax each call (atomics accumulate into it)
// ---------------------------------------------------------------------------
__global__ void init_kernel() {
    int i = blockIdx.x * blockDim.x + threadIdx.x;
    if (i < BN * HWN) g_colmax[i] = 0.0f;
}

// ---------------------------------------------------------------------------
// 1) fused QKV 1x1-conv GEMM:  X[b,o,n] = sum_c W[o,c] * fuse[b,c,n] + bias[o]
//    Writes: g_Q, g_V fp32 [b][c][n];  g_Qb, g_Kb bf16 transposed [b][n][c].
// ---------------------------------------------------------------------------
__global__ __launch_bounds__(256) void qkv_kernel(
    const float* __restrict__ fuse,
    const float* __restrict__ Wq, const float* __restrict__ bq,
    const float* __restrict__ Wk, const float* __restrict__ bk,
    const float* __restrict__ Wv, const float* __restrict__ bv)
{
    __shared__ float sF [16][68];
    __shared__ float sWq[16][68];
    __shared__ float sWk[16][68];
    __shared__ float sWv[16][68];

    const int b  = blockIdx.z;
    const int o0 = blockIdx.y * 64;
    const int n0 = blockIdx.x * 64;
    const int tid = threadIdx.x;
    const int tx = tid & 15;      // n sub-tile
    const int ty = tid >> 4;      // o sub-tile

    float aq[4][4], ak[4][4], av[4][4];
#pragma unroll
    for (int i = 0; i < 4; i++)
#pragma unroll
        for (int j = 0; j < 4; j++) { aq[i][j] = 0.f; ak[i][j] = 0.f; av[i][j] = 0.f; }

    const float* fbase = fuse + (size_t)b * CHWN + n0;

    const int f_ck = tid >> 4;
    const int f_nn = (tid & 15) * 4;
    const int w_oo = tid >> 2;
    const int w_ck = (tid & 3) * 4;

    for (int c0 = 0; c0 < CN; c0 += 16) {
        __syncthreads();
        {
            float4 f4 = *reinterpret_cast<const float4*>(&fbase[(c0 + f_ck) * HWN + f_nn]);
            *reinterpret_cast<float4*>(&sF[f_ck][f_nn]) = f4;
        }
        {
            float4 q4 = *reinterpret_cast<const float4*>(&Wq[(o0 + w_oo) * CN + c0 + w_ck]);
            float4 k4 = *reinterpret_cast<const float4*>(&Wk[(o0 + w_oo) * CN + c0 + w_ck]);
            float4 v4 = *reinterpret_cast<const float4*>(&Wv[(o0 + w_oo) * CN + c0 + w_ck]);
            sWq[w_ck + 0][w_oo] = q4.x; sWq[w_ck + 1][w_oo] = q4.y;
            sWq[w_ck + 2][w_oo] = q4.z; sWq[w_ck + 3][w_oo] = q4.w;
            sWk[w_ck + 0][w_oo] = k4.x; sWk[w_ck + 1][w_oo] = k4.y;
            sWk[w_ck + 2][w_oo] = k4.z; sWk[w_ck + 3][w_oo] = k4.w;
            sWv[w_ck + 0][w_oo] = v4.x; sWv[w_ck + 1][w_oo] = v4.y;
            sWv[w_ck + 2][w_oo] = v4.z; sWv[w_ck + 3][w_oo] = v4.w;
        }
        __syncthreads();
#pragma unroll
        for (int ck = 0; ck < 16; ck++) {
            float4 bf4 = *reinterpret_cast<const float4*>(&sF [ck][tx * 4]);
            float4 q4  = *reinterpret_cast<const float4*>(&sWq[ck][ty * 4]);
            float4 k4  = *reinterpret_cast<const float4*>(&sWk[ck][ty * 4]);
            float4 v4  = *reinterpret_cast<const float4*>(&sWv[ck][ty * 4]);
            float bfr[4] = {bf4.x, bf4.y, bf4.z, bf4.w};
            float qr [4] = {q4.x,  q4.y,  q4.z,  q4.w };
            float kr [4] = {k4.x,  k4.y,  k4.z,  k4.w };
            float vr [4] = {v4.x,  v4.y,  v4.z,  v4.w };
#pragma unroll
            for (int i = 0; i < 4; i++)
#pragma unroll
                for (int j = 0; j < 4; j++) {
                    aq[i][j] += qr[i] * bfr[j];
                    ak[i][j] += kr[i] * bfr[j];
                    av[i][j] += vr[i] * bfr[j];
                }
        }
    }

    float bqv[4], bkv[4], bvv[4];
#pragma unroll
    for (int i = 0; i < 4; i++) {
        int o = o0 + ty * 4 + i;
        bqv[i] = bq[o]; bkv[i] = bk[o]; bvv[i] = bv[o];
    }

    // fp32 Q and V in [c][n]
#pragma unroll
    for (int i = 0; i < 4; i++) {
        const size_t base = (size_t)b * CHWN + (size_t)(o0 + ty * 4 + i) * HWN + n0 + tx * 4;
        float4 oq = make_float4(aq[i][0] + bqv[i], aq[i][1] + bqv[i], aq[i][2] + bqv[i], aq[i][3] + bqv[i]);
        float4 ov = make_float4(av[i][0] + bvv[i], av[i][1] + bvv[i], av[i][2] + bvv[i], av[i][3] + bvv[i]);
        *reinterpret_cast<float4*>(&g_Q[base]) = oq;
        *reinterpret_cast<float4*>(&g_V[base]) = ov;
    }

    // bf16 Q/K transposed [n][c]: 4 consecutive c per thread = 8-byte store
#pragma unroll
    for (int j = 0; j < 4; j++) {
        const int n = n0 + tx * 4 + j;
        const size_t tbase = (size_t)b * CHWN + (size_t)n * CN + o0 + ty * 4;
        __nv_bfloat162 q01 = __floats2bfloat162_rn(aq[0][j] + bqv[0], aq[1][j] + bqv[1]);
        __nv_bfloat162 q23 = __floats2bfloat162_rn(aq[2][j] + bqv[2], aq[3][j] + bqv[3]);
        __nv_bfloat162 k01 = __floats2bfloat162_rn(ak[0][j] + bkv[0], ak[1][j] + bkv[1]);
        __nv_bfloat162 k23 = __floats2bfloat162_rn(ak[2][j] + bkv[2], ak[3][j] + bkv[3]);
        uint2 qp = make_uint2(*(uint32_t*)&q01, *(uint32_t*)&q23);
        uint2 kp = make_uint2(*(uint32_t*)&k01, *(uint32_t*)&k23);
        *reinterpret_cast<uint2*>(&g_Qb[tbase]) = qp;
        *reinterpret_cast<uint2*>(&g_Kb[tbase]) = kp;
    }
}

// ---------------------------------------------------------------------------
// 2) Q_mask[(c%4)*4096 + n] = max over b (4) and q (64, c = 4q + c%4) of Q[b,c,n]
// ---------------------------------------------------------------------------
__global__ void qmask_kernel() {
    int col = blockIdx.x * blockDim.x + threadIdx.x;   // 0..16383
    if (col >= 4 * HWN) return;
    int cm = col >> 12;           // c % 4
    int n  = col & (HWN - 1);
    float mx = -3.4e38f;
#pragma unroll 4
    for (int b = 0; b < BN; b++) {
        const float* base = &g_Q[(size_t)b * CHWN + n];
        for (int q = 0; q < 64; q++)
            mx = fmaxf(mx, base[(size_t)(4 * q + cm) * HWN]);
    }
    g_Qmask[col] = mx;
}

// ---------------------------------------------------------------------------
// 3) scores + batch-softmax + column-max reduction  (bf16 mma + ldmatrix)
//    Block: 64(n) x 64(m) x 4(b), 8 warps = 4(n-tiles of 16) x 2(m-halves of 32).
//    4-stage cp.async pipeline, KC=16 per stage, wait_group 2 (3 loads in
//    flight).  48B row pitch (conflict-free ldmatrix + stores).  2 CTAs/SM.
// ---------------------------------------------------------------------------
#define KC      16
#define PITCH   12                      // b32 per row (8 data + 4 pad)
#define TILE32  (64 * PITCH)            // per-b tile, b32 units = 768
#define OPST32  (4 * TILE32)            // per operand per stage = 3072
#define NSTAGE  4
#define SQ32    (NSTAGE * OPST32)       // 12288
#define RED32   (2 * SQ32)              // sRed after Q and K regions
#define SCORES_SMEM_BYTES (RED32 * 4 + 256 * 4)
#define NCHUNK  (CN / KC)               // 16

__global__ __launch_bounds__(256, 2) void scores_kernel() {
    extern __shared__ uint32_t smem[];
    uint32_t* sQ = smem;                 // [stage][b][row 64][PITCH]
    uint32_t* sK = smem + SQ32;
    int* sRed = (int*)(smem + RED32);    // [4][64]

    const uint32_t sQ_u = (uint32_t)__cvta_generic_to_shared(sQ);
    const uint32_t sK_u = (uint32_t)__cvta_generic_to_shared(sK);

    const int m0 = blockIdx.x * 64;
    const int n0 = blockIdx.y * 64;
    const int tid = threadIdx.x;
    const int warp = tid >> 5;
    const int lane = tid & 31;
    const int tg  = lane & 3;     // 0..3
    const int wn = warp & 3;      // n-tile (16 rows each)
    const int wm = warp >> 2;     // m-half (32 cols each)

    sRed[tid] = 0;

    float acc[4][4][4];           // [b][j(m8 tile)][e(frag elem)]
#pragma unroll
    for (int b = 0; b < 4; b++)
#pragma unroll
        for (int j = 0; j < 4; j++)
#pragma unroll
            for (int e = 0; e < 4; e++) acc[b][j][e] = 0.f;

    // ldmatrix lane-address byte offsets (within one b-tile, 48B rows)
    // A (x4): lanes 0-15 rows wn*16+(lane&15) khalf0; lanes 16-31 same rows khalf1
    const uint32_t a_off = (uint32_t)((wn * 16 + (lane & 15)) * 48 + (lane >> 4) * 16);
    // B (x4 = 2 j-tiles of 8 rows): row = wm*32 + ((lane>>4)<<3) + (lane&7),
    // k-half = (lane>>3)&1
    const uint32_t b_off = (uint32_t)((wm * 32 + ((lane >> 4) << 3) + (lane & 7)) * 48 +
                                      ((lane >> 3) & 1) * 16);

    // ---- async load of one KC=16 chunk into stage s ----
    // per operand: 4b x 64 rows x 2 segs(16B) = 512 cp.asyncs; row-fastest slot
    // mapping keeps smem stores conflict-free.
    auto issue_chunk = [&](int c, int s) {
        const int kb = c * KC;           // bf16 offset within row
#pragma unroll
        for (int it = 0; it < 2; it++) {
            int slot = it * 256 + tid;   // 0..511
            int row = slot & 63;
            int seg = (slot >> 6) & 1;
            int b   = slot >> 7;
            int d = s * OPST32 + b * TILE32 + row * PITCH + seg * 4;
            cpasync16(&sQ[d], &g_Qb[(size_t)b * CHWN + (size_t)(n0 + row) * CN + kb + seg * 8]);
            cpasync16(&sK[d], &g_Kb[(size_t)b * CHWN + (size_t)(m0 + row) * CN + kb + seg * 8]);
        }
    };

    issue_chunk(0, 0); cpcommit();
    issue_chunk(1, 1); cpcommit();
    issue_chunk(2, 2); cpcommit();

#pragma unroll 1
    for (int c = 0; c < NCHUNK; c++) {
        if (c < NCHUNK - 2)      asm volatile("cp.async.wait_group 2;\n" ::: "memory");
        else if (c == NCHUNK - 2) asm volatile("cp.async.wait_group 1;\n" ::: "memory");
        else                      asm volatile("cp.async.wait_group 0;\n" ::: "memory");
        __syncthreads();          // all warps done with stage (c-1)&3; chunk c arrived

        if (c + 3 < NCHUNK) { issue_chunk(c + 3, (c + 3) & 3); cpcommit(); }

        const int s = c & 3;
        const uint32_t qbase = sQ_u + (uint32_t)(s * OPST32 * 4);
        const uint32_t kbase = sK_u + (uint32_t)(s * OPST32 * 4);
#pragma unroll
        for (int b = 0; b < 4; b++) {
            const uint32_t tb = (uint32_t)(b * TILE32 * 4);
            uint32_t A0, A1, A2, A3;
            ldmx4(A0, A1, A2, A3, qbase + tb + a_off);
#pragma unroll
            for (int jp = 0; jp < 2; jp++) {   // 2 j-tiles per B-ldmatrix
                uint32_t B0, B1, B2, B3;
                ldmx4(B0, B1, B2, B3, kbase + tb + b_off + jp * 768);
                const int j0 = jp * 2;
                asm volatile(
                    "mma.sync.aligned.m16n8k16.row.col.f32.bf16.bf16.f32 "
                    "{%0,%1,%2,%3}, {%4,%5,%6,%7}, {%8,%9}, {%0,%1,%2,%3};"
                    : "+f"(acc[b][j0][0]), "+f"(acc[b][j0][1]),
                      "+f"(acc[b][j0][2]), "+f"(acc[b][j0][3])
                    : "r"(A0), "r"(A1), "r"(A2), "r"(A3), "r"(B0), "r"(B1));
                asm volatile(
                    "mma.sync.aligned.m16n8k16.row.col.f32.bf16.bf16.f32 "
                    "{%0,%1,%2,%3}, {%4,%5,%6,%7}, {%8,%9}, {%0,%1,%2,%3};"
                    : "+f"(acc[b][j0+1][0]), "+f"(acc[b][j0+1][1]),
                      "+f"(acc[b][j0+1][2]), "+f"(acc[b][j0+1][3])
                    : "r"(A0), "r"(A1), "r"(A2), "r"(A3), "r"(B2), "r"(B3));
            }
        }
    }

    // ---- epilogue: softmax over b per (n,m); fold max over the thread's two
    //      n-rows; atomicMax into per-block column max sRed[b][m_local] ----
#pragma unroll
    for (int j = 0; j < 4; j++) {
#pragma unroll
        for (int p = 0; p < 2; p++) {         // column parity (2*tg + p)
            float colv[4];
#pragma unroll
            for (int b = 0; b < 4; b++) colv[b] = 0.f;
#pragma unroll
            for (int rr = 0; rr < 2; rr++) {  // the two n-rows (gid, gid+8)
                int e = rr * 2 + p;
                float sv[4];
                float mx = -3.4e38f;
#pragma unroll
                for (int b = 0; b < 4; b++) { sv[b] = acc[b][j][e] * SCALE; mx = fmaxf(mx, sv[b]); }
                float ex[4], sum = 0.f;
#pragma unroll
                for (int b = 0; b < 4; b++) { ex[b] = __expf(sv[b] - mx); sum += ex[b]; }
                float inv = 1.0f / sum;
#pragma unroll
                for (int b = 0; b < 4; b++) colv[b] = fmaxf(colv[b], ex[b] * inv);
            }
            int m_local = wm * 32 + j * 8 + tg * 2 + p;
#pragma unroll
            for (int b = 0; b < 4; b++)
                atomicMax(&sRed[b * 64 + m_local], __float_as_int(colv[b]));
        }
    }
    __syncthreads();

    {
        int b  = tid >> 6;
        int mm = tid & 63;
        atomicMax(reinterpret_cast<int*>(&g_colmax[(size_t)b * HWN + m0 + mm]), sRed[tid]);
    }
}

// ---------------------------------------------------------------------------
// 4) m2[b*64 + h_k] = max over w_k of colmax[b, h_k*64 + w_k]
// ---------------------------------------------------------------------------
__global__ void m2_kernel() {
    int r = threadIdx.x;          // 0..255, single block
    int b = r >> 6, hk = r & 63;
    const float* base = &g_colmax[(size_t)b * HWN + hk * 64];
    float mx = 0.f;
#pragma unroll
    for (int wk = 0; wk < 64; wk++) mx = fmaxf(mx, base[wk]);
    g_m2[r] = mx;
}

// ---------------------------------------------------------------------------
// 5) out[b,c,n] = V * (1 + m2[b*64 + c/4] * Qmask[(c%4)*4096 + n])
// ---------------------------------------------------------------------------
__global__ void out_kernel(float* __restrict__ out) {
    int f = blockIdx.x * blockDim.x + threadIdx.x;     // float4 index
    if (f >= BN * CHWN / 4) return;
    int n4 = f & (HWN / 4 - 1);
    int bc = f >> 10;
    int c  = bc & (CN - 1);
    int b  = bc >> 8;
    int n  = n4 * 4;
    float m2v = g_m2[b * 64 + (c >> 2)];
    float4 qm = *reinterpret_cast<const float4*>(&g_Qmask[(c & 3) * HWN + n]);
    float4 v  = reinterpret_cast<const float4*>(g_V)[f];
    float4 o;
    o.x = v.x * fmaf(m2v, qm.x, 1.0f);
    o.y = v.y * fmaf(m2v, qm.y, 1.0f);
    o.z = v.z * fmaf(m2v, qm.z, 1.0f);
    o.w = v.w * fmaf(m2v, qm.w, 1.0f);
    reinterpret_cast<float4*>(out)[f] = o;
}

// ---------------------------------------------------------------------------
extern "C" void kernel_launch(void* const* d_in, const int* in_sizes, int n_in,
                              void* d_out, int out_size) {
    const float* fuse = (const float*)d_in[0];
    const float* Wq   = (const float*)d_in[1];
    const float* bq   = (const float*)d_in[2];
    const float* Wk   = (const float*)d_in[3];
    const float* bk   = (const float*)d_in[4];
    const float* Wv   = (const float*)d_in[5];
    const float* bv   = (const float*)d_in[6];
    float* out = (float*)d_out;

    cudaFuncSetAttribute(scores_kernel,
                         cudaFuncAttributeMaxDynamicSharedMemorySize,
                         SCORES_SMEM_BYTES);

    init_kernel<<<(BN * HWN + 255) / 256, 256>>>();

    dim3 gq(HWN / 64, CN / 64, BN);
    qkv_kernel<<<gq, 256>>>(fuse, Wq, bq, Wk, bk, Wv, bv);

    qmask_kernel<<<(4 * HWN + 255) / 256, 256>>>();

    dim3 gs(HWN / 64, HWN / 64);
    scores_kernel<<<gs, 256, SCORES_SMEM_BYTES>>>();

    m2_kernel<<<1, 256>>>();

    out_kernel<<<(BN * CHWN / 4 + 255) / 256, 256>>>(out);
}

// round 10
// speedup vs baseline: 1.2707x; 1.2707x over previous
#include <cuda_runtime.h>
#include <cuda_bf16.h>
#include <math.h>
#include <stdint.h>

// Problem constants
#define BN   4
#define CN   256
#define HN   64
#define WN   64
#define HWN  4096
#define CHWN (CN * HWN)     // 1048576
#define SCALE 0.0625f       // 1/sqrt(256)

// ---------------------------------------------------------------------------
// Scratch (device globals; no allocations allowed)
// ---------------------------------------------------------------------------
__device__ float g_Q [BN * CHWN];            // fp32 Q, [b][c][n]  (for Q_mask)
__device__ float g_V [BN * CHWN];            // fp32 V, [b][c][n]
__device__ __nv_bfloat16 g_Qb[BN * CHWN];    // bf16 Q, TRANSPOSED [b][n][c]
__device__ __nv_bfloat16 g_Kb[BN * CHWN];    // bf16 K, TRANSPOSED [b][m][c]
__device__ float g_colmax[BN * HWN];         // max over n of soft[b,n,m]  (positive)
__device__ float g_Qmask[4 * HWN];           // indexed by (c%4)*4096 + n
__device__ float g_m2[BN * HN];              // indexed by b*64 + h_k

__device__ __forceinline__ void cpasync16(void* dst, const void* src) {
    unsigned s = (unsigned)__cvta_generic_to_shared(dst);
    asm volatile("cp.async.cg.shared.global [%0], [%1], 16;\n" :: "r"(s), "l"(src));
}
__device__ __forceinline__ void cpcommit() { asm volatile("cp.async.commit_group;\n"); }
__device__ __forceinline__ void cpwait0()  { asm volatile("cp.async.wait_group 0;\n"); }

__device__ __forceinline__ void ldmx4(uint32_t& r0, uint32_t& r1, uint32_t& r2, uint32_t& r3,
                                      uint32_t addr) {
    asm volatile("ldmatrix.sync.aligned.m8n8.x4.shared.b16 {%0,%1,%2,%3}, [%4];"
                 : "=r"(r0), "=r"(r1), "=r"(r2), "=r"(r3) : "r"(addr));
}

// ---------------------------------------------------------------------------
// 0) zero colmax each call (atomics accumulate into it)
// ---------------------------------------------------------------------------
__global__ void init_kernel() {
    int i = blockIdx.x * blockDim.x + threadIdx.x;
    if (i < BN * HWN) g_colmax[i] = 0.0f;
}

// ---------------------------------------------------------------------------
// 1) fused QKV 1x1-conv GEMM:  X[b,o,n] = sum_c W[o,c] * fuse[b,c,n] + bias[o]
//    Writes: g_Q, g_V fp32 [b][c][n];  g_Qb, g_Kb bf16 transposed [b][n][c].
// ---------------------------------------------------------------------------
__global__ __launch_bounds__(256) void qkv_kernel(
    const float* __restrict__ fuse,
    const float* __restrict__ Wq, const float* __restrict__ bq,
    const float* __restrict__ Wk, const float* __restrict__ bk,
    const float* __restrict__ Wv, const float* __restrict__ bv)
{
    __shared__ float sF [16][68];
    __shared__ float sWq[16][68];
    __shared__ float sWk[16][68];
    __shared__ float sWv[16][68];

    const int b  = blockIdx.z;
    const int o0 = blockIdx.y * 64;
    const int n0 = blockIdx.x * 64;
    const int tid = threadIdx.x;
    const int tx = tid & 15;      // n sub-tile
    const int ty = tid >> 4;      // o sub-tile

    float aq[4][4], ak[4][4], av[4][4];
#pragma unroll
    for (int i = 0; i < 4; i++)
#pragma unroll
        for (int j = 0; j < 4; j++) { aq[i][j] = 0.f; ak[i][j] = 0.f; av[i][j] = 0.f; }

    const float* fbase = fuse + (size_t)b * CHWN + n0;

    const int f_ck = tid >> 4;
    const int f_nn = (tid & 15) * 4;
    const int w_oo = tid >> 2;
    const int w_ck = (tid & 3) * 4;

    for (int c0 = 0; c0 < CN; c0 += 16) {
        __syncthreads();
        {
            float4 f4 = *reinterpret_cast<const float4*>(&fbase[(c0 + f_ck) * HWN + f_nn]);
            *reinterpret_cast<float4*>(&sF[f_ck][f_nn]) = f4;
        }
        {
            float4 q4 = *reinterpret_cast<const float4*>(&Wq[(o0 + w_oo) * CN + c0 + w_ck]);
            float4 k4 = *reinterpret_cast<const float4*>(&Wk[(o0 + w_oo) * CN + c0 + w_ck]);
            float4 v4 = *reinterpret_cast<const float4*>(&Wv[(o0 + w_oo) * CN + c0 + w_ck]);
            sWq[w_ck + 0][w_oo] = q4.x; sWq[w_ck + 1][w_oo] = q4.y;
            sWq[w_ck + 2][w_oo] = q4.z; sWq[w_ck + 3][w_oo] = q4.w;
            sWk[w_ck + 0][w_oo] = k4.x; sWk[w_ck + 1][w_oo] = k4.y;
            sWk[w_ck + 2][w_oo] = k4.z; sWk[w_ck + 3][w_oo] = k4.w;
            sWv[w_ck + 0][w_oo] = v4.x; sWv[w_ck + 1][w_oo] = v4.y;
            sWv[w_ck + 2][w_oo] = v4.z; sWv[w_ck + 3][w_oo] = v4.w;
        }
        __syncthreads();
#pragma unroll
        for (int ck = 0; ck < 16; ck++) {
            float4 bf4 = *reinterpret_cast<const float4*>(&sF [ck][tx * 4]);
            float4 q4  = *reinterpret_cast<const float4*>(&sWq[ck][ty * 4]);
            float4 k4  = *reinterpret_cast<const float4*>(&sWk[ck][ty * 4]);
            float4 v4  = *reinterpret_cast<const float4*>(&sWv[ck][ty * 4]);
            float bfr[4] = {bf4.x, bf4.y, bf4.z, bf4.w};
            float qr [4] = {q4.x,  q4.y,  q4.z,  q4.w };
            float kr [4] = {k4.x,  k4.y,  k4.z,  k4.w };
            float vr [4] = {v4.x,  v4.y,  v4.z,  v4.w };
#pragma unroll
            for (int i = 0; i < 4; i++)
#pragma unroll
                for (int j = 0; j < 4; j++) {
                    aq[i][j] += qr[i] * bfr[j];
                    ak[i][j] += kr[i] * bfr[j];
                    av[i][j] += vr[i] * bfr[j];
                }
        }
    }

    float bqv[4], bkv[4], bvv[4];
#pragma unroll
    for (int i = 0; i < 4; i++) {
        int o = o0 + ty * 4 + i;
        bqv[i] = bq[o]; bkv[i] = bk[o]; bvv[i] = bv[o];
    }

    // fp32 Q and V in [c][n]
#pragma unroll
    for (int i = 0; i < 4; i++) {
        const size_t base = (size_t)b * CHWN + (size_t)(o0 + ty * 4 + i) * HWN + n0 + tx * 4;
        float4 oq = make_float4(aq[i][0] + bqv[i], aq[i][1] + bqv[i], aq[i][2] + bqv[i], aq[i][3] + bqv[i]);
        float4 ov = make_float4(av[i][0] + bvv[i], av[i][1] + bvv[i], av[i][2] + bvv[i], av[i][3] + bvv[i]);
        *reinterpret_cast<float4*>(&g_Q[base]) = oq;
        *reinterpret_cast<float4*>(&g_V[base]) = ov;
    }

    // bf16 Q/K transposed [n][c]: 4 consecutive c per thread = 8-byte store
#pragma unroll
    for (int j = 0; j < 4; j++) {
        const int n = n0 + tx * 4 + j;
        const size_t tbase = (size_t)b * CHWN + (size_t)n * CN + o0 + ty * 4;
        __nv_bfloat162 q01 = __floats2bfloat162_rn(aq[0][j] + bqv[0], aq[1][j] + bqv[1]);
        __nv_bfloat162 q23 = __floats2bfloat162_rn(aq[2][j] + bqv[2], aq[3][j] + bqv[3]);
        __nv_bfloat162 k01 = __floats2bfloat162_rn(ak[0][j] + bkv[0], ak[1][j] + bkv[1]);
        __nv_bfloat162 k23 = __floats2bfloat162_rn(ak[2][j] + bkv[2], ak[3][j] + bkv[3]);
        uint2 qp = make_uint2(*(uint32_t*)&q01, *(uint32_t*)&q23);
        uint2 kp = make_uint2(*(uint32_t*)&k01, *(uint32_t*)&k23);
        *reinterpret_cast<uint2*>(&g_Qb[tbase]) = qp;
        *reinterpret_cast<uint2*>(&g_Kb[tbase]) = kp;
    }
}

// ---------------------------------------------------------------------------
// 2) Q_mask[(c%4)*4096 + n] = max over b (4) and q (64, c = 4q + c%4) of Q[b,c,n]
// ---------------------------------------------------------------------------
__global__ void qmask_kernel() {
    int col = blockIdx.x * blockDim.x + threadIdx.x;   // 0..16383
    if (col >= 4 * HWN) return;
    int cm = col >> 12;           // c % 4
    int n  = col & (HWN - 1);
    float mx = -3.4e38f;
#pragma unroll 4
    for (int b = 0; b < BN; b++) {
        const float* base = &g_Q[(size_t)b * CHWN + n];
        for (int q = 0; q < 64; q++)
            mx = fmaxf(mx, base[(size_t)(4 * q + cm) * HWN]);
    }
    g_Qmask[col] = mx;
}

// ---------------------------------------------------------------------------
// 3) scores + batch-softmax + column-max reduction  (bf16 mma + ldmatrix)
//    Block: 128(n) x 64(m) x 4(b), 512 threads, 16 warps =
//    8(n-tiles of 16) x 2(m-halves of 32).  Warp tile 16n x 32m x 4b,
//    64 f32 acc/thread (same as before — register pressure unchanged).
//    KC=32, 2-stage cp.async, 80B row pitch, one barrier per chunk, 1 CTA/SM.
// ---------------------------------------------------------------------------
#define KC      32
#define PITCH   20                      // b32 per row (16 data + 4 pad)
#define ATILE32 (128 * PITCH)           // A per-b tile = 2560 b32
#define BTILE32 (64 * PITCH)            // B per-b tile = 1280 b32
#define AOPST32 (4 * ATILE32)           // A per stage = 10240
#define BOPST32 (4 * BTILE32)           // B per stage = 5120
#define SK_BASE (2 * AOPST32)           // K region after A's two stages
#define RED32   (SK_BASE + 2 * BOPST32) // sRed offset
#define SCORES_SMEM_BYTES (RED32 * 4 + 256 * 4)
#define NCHUNK  (CN / KC)               // 8

__global__ __launch_bounds__(512, 1) void scores_kernel() {
    extern __shared__ uint32_t smem[];
    uint32_t* sQ = smem;                 // [stage][b][row 128][PITCH]
    uint32_t* sK = smem + SK_BASE;       // [stage][b][row 64][PITCH]
    int* sRed = (int*)(smem + RED32);    // [4][64]

    const uint32_t sQ_u = (uint32_t)__cvta_generic_to_shared(sQ);
    const uint32_t sK_u = (uint32_t)__cvta_generic_to_shared(sK);

    const int m0 = blockIdx.x * 64;
    const int n0 = blockIdx.y * 128;
    const int tid = threadIdx.x;
    const int warp = tid >> 5;
    const int lane = tid & 31;
    const int tg  = lane & 3;     // 0..3
    const int wn = warp & 7;      // n-tile (16 rows each, 8 tiles)
    const int wm = warp >> 3;     // m-half (32 cols each)

    if (tid < 256) sRed[tid] = 0;

    float acc[4][4][4];           // [b][j(m8 tile)][e(frag elem)]
#pragma unroll
    for (int b = 0; b < 4; b++)
#pragma unroll
        for (int j = 0; j < 4; j++)
#pragma unroll
            for (int e = 0; e < 4; e++) acc[b][j][e] = 0.f;

    // ldmatrix lane-address byte offsets (within one b-tile, 80B rows)
    const uint32_t a_off = (uint32_t)((wn * 16 + (lane & 15)) * 80 + (lane >> 4) * 16);
    const uint32_t b_off = (uint32_t)((wm * 32 + ((lane >> 4) << 3) + (lane & 7)) * 80 +
                                      ((lane >> 3) & 1) * 16);

    // ---- async load of one KC=32 chunk into stage s ----
    // A: 4b x 128 rows x 4 segs = 2048 cp.asyncs (4/thread);
    // B: 4b x  64 rows x 4 segs = 1024 cp.asyncs (2/thread).
    auto issue_chunk = [&](int c, int s) {
        const int kb = c * KC;           // bf16 offset within row
#pragma unroll
        for (int it = 0; it < 4; it++) {
            int slot = it * 512 + tid;   // 0..2047
            int b   = slot >> 9;
            int row = (slot >> 2) & 127;
            int seg = slot & 3;          // 16B segment (8 bf16)
            int d = s * AOPST32 + b * ATILE32 + row * PITCH + seg * 4;
            cpasync16(&sQ[d], &g_Qb[(size_t)b * CHWN + (size_t)(n0 + row) * CN + kb + seg * 8]);
        }
#pragma unroll
        for (int it = 0; it < 2; it++) {
            int slot = it * 512 + tid;   // 0..1023
            int b   = slot >> 8;
            int row = (slot >> 2) & 63;
            int seg = slot & 3;
            int d = s * BOPST32 + b * BTILE32 + row * PITCH + seg * 4;
            cpasync16(&sK[d], &g_Kb[(size_t)b * CHWN + (size_t)(m0 + row) * CN + kb + seg * 8]);
        }
    };

    issue_chunk(0, 0);
    cpcommit();

    for (int c = 0; c < NCHUNK; c++) {
        cpwait0();
        __syncthreads();      // orders prior stage-s reads before overwriting it
        if (c < NCHUNK - 1) { issue_chunk(c + 1, (c + 1) & 1); cpcommit(); }

        const int s = c & 1;
        const uint32_t qbase = sQ_u + (uint32_t)(s * AOPST32 * 4);
        const uint32_t kbase = sK_u + (uint32_t)(s * BOPST32 * 4);
#pragma unroll
        for (int kk = 0; kk < 2; kk++) {           // two k16 steps per chunk
            const uint32_t kbyte = kk * 32;
#pragma unroll
            for (int b = 0; b < 4; b++) {
                const uint32_t atb = (uint32_t)(b * ATILE32 * 4);
                const uint32_t btb = (uint32_t)(b * BTILE32 * 4);
                uint32_t A0, A1, A2, A3;
                ldmx4(A0, A1, A2, A3, qbase + atb + a_off + kbyte);
#pragma unroll
                for (int jp = 0; jp < 2; jp++) {   // 2 j-tiles per B-ldmatrix
                    uint32_t B0, B1, B2, B3;
                    ldmx4(B0, B1, B2, B3, kbase + btb + b_off + jp * 1280 + kbyte);
                    const int j0 = jp * 2;
                    asm volatile(
                        "mma.sync.aligned.m16n8k16.row.col.f32.bf16.bf16.f32 "
                        "{%0,%1,%2,%3}, {%4,%5,%6,%7}, {%8,%9}, {%0,%1,%2,%3};"
                        : "+f"(acc[b][j0][0]), "+f"(acc[b][j0][1]),
                          "+f"(acc[b][j0][2]), "+f"(acc[b][j0][3])
                        : "r"(A0), "r"(A1), "r"(A2), "r"(A3), "r"(B0), "r"(B1));
                    asm volatile(
                        "mma.sync.aligned.m16n8k16.row.col.f32.bf16.bf16.f32 "
                        "{%0,%1,%2,%3}, {%4,%5,%6,%7}, {%8,%9}, {%0,%1,%2,%3};"
                        : "+f"(acc[b][j0+1][0]), "+f"(acc[b][j0+1][1]),
                          "+f"(acc[b][j0+1][2]), "+f"(acc[b][j0+1][3])
                        : "r"(A0), "r"(A1), "r"(A2), "r"(A3), "r"(B2), "r"(B3));
                }
            }
        }
    }

    // ---- epilogue: softmax over b per (n,m); fold max over the thread's two
    //      n-rows; atomicMax into per-block column max sRed[b][m_local] ----
#pragma unroll
    for (int j = 0; j < 4; j++) {
#pragma unroll
        for (int p = 0; p < 2; p++) {         // column parity (2*tg + p)
            float colv[4];
#pragma unroll
            for (int b = 0; b < 4; b++) colv[b] = 0.f;
#pragma unroll
            for (int rr = 0; rr < 2; rr++) {  // the two n-rows (gid, gid+8)
                int e = rr * 2 + p;
                float sv[4];
                float mx = -3.4e38f;
#pragma unroll
                for (int b = 0; b < 4; b++) { sv[b] = acc[b][j][e] * SCALE; mx = fmaxf(mx, sv[b]); }
                float ex[4], sum = 0.f;
#pragma unroll
                for (int b = 0; b < 4; b++) { ex[b] = __expf(sv[b] - mx); sum += ex[b]; }
                float inv = 1.0f / sum;
#pragma unroll
                for (int b = 0; b < 4; b++) colv[b] = fmaxf(colv[b], ex[b] * inv);
            }
            int m_local = wm * 32 + j * 8 + tg * 2 + p;
#pragma unroll
            for (int b = 0; b < 4; b++)
                atomicMax(&sRed[b * 64 + m_local], __float_as_int(colv[b]));
        }
    }
    __syncthreads();

    if (tid < 256) {
        int b  = tid >> 6;
        int mm = tid & 63;
        atomicMax(reinterpret_cast<int*>(&g_colmax[(size_t)b * HWN + m0 + mm]), sRed[tid]);
    }
}

// ---------------------------------------------------------------------------
// 4) m2[b*64 + h_k] = max over w_k of colmax[b, h_k*64 + w_k]
// ---------------------------------------------------------------------------
__global__ void m2_kernel() {
    int r = threadIdx.x;          // 0..255, single block
    int b = r >> 6, hk = r & 63;
    const float* base = &g_colmax[(size_t)b * HWN + hk * 64];
    float mx = 0.f;
#pragma unroll
    for (int wk = 0; wk < 64; wk++) mx = fmaxf(mx, base[wk]);
    g_m2[r] = mx;
}

// ---------------------------------------------------------------------------
// 5) out[b,c,n] = V * (1 + m2[b*64 + c/4] * Qmask[(c%4)*4096 + n])
// ---------------------------------------------------------------------------
__global__ void out_kernel(float* __restrict__ out) {
    int f = blockIdx.x * blockDim.x + threadIdx.x;     // float4 index
    if (f >= BN * CHWN / 4) return;
    int n4 = f & (HWN / 4 - 1);
    int bc = f >> 10;
    int c  = bc & (CN - 1);
    int b  = bc >> 8;
    int n  = n4 * 4;
    float m2v = g_m2[b * 64 + (c >> 2)];
    float4 qm = *reinterpret_cast<const float4*>(&g_Qmask[(c & 3) * HWN + n]);
    float4 v  = reinterpret_cast<const float4*>(g_V)[f];
    float4 o;
    o.x = v.x * fmaf(m2v, qm.x, 1.0f);
    o.y = v.y * fmaf(m2v, qm.y, 1.0f);
    o.z = v.z * fmaf(m2v, qm.z, 1.0f);
    o.w = v.w * fmaf(m2v, qm.w, 1.0f);
    reinterpret_cast<float4*>(out)[f] = o;
}

// ---------------------------------------------------------------------------
extern "C" void kernel_launch(void* const* d_in, const int* in_sizes, int n_in,
                              void* d_out, int out_size) {
    const float* fuse = (const float*)d_in[0];
    const float* Wq   = (const float*)d_in[1];
    const float* bq   = (const float*)d_in[2];
    const float* Wk   = (const float*)d_in[3];
    const float* bk   = (const float*)d_in[4];
    const float* Wv   = (const float*)d_in[5];
    const float* bv   = (const float*)d_in[6];
    float* out = (float*)d_out;

    cudaFuncSetAttribute(scores_kernel,
                         cudaFuncAttributeMaxDynamicSharedMemorySize,
                         SCORES_SMEM_BYTES);

    init_kernel<<<(BN * HWN + 255) / 256, 256>>>();

    dim3 gq(HWN / 64, CN / 64, BN);
    qkv_kernel<<<gq, 256>>>(fuse, Wq, bq, Wk, bk, Wv, bv);

    qmask_kernel<<<(4 * HWN + 255) / 256, 256>>>();

    dim3 gs(HWN / 64, HWN / 128);   // 64 m-tiles x 32 n-tiles
    scores_kernel<<<gs, 512, SCORES_SMEM_BYTES>>>();

    m2_kernel<<<1, 256>>>();

    out_kernel<<<(BN * CHWN / 4 + 255) / 256, 256>>>(out);
}